// round 4
// baseline (speedup 1.0000x reference)
#include <cuda_runtime.h>
#include <math.h>
#include <stdint.h>

// ============================================================================
// FusedExpertsWrapper — TF32 mma.sync, 512-thread CTAs (16 warps) for latency
// hiding. Tile 128x256, BK=32, 4-stage cp.async pipeline, single barrier/chunk.
//   GEMM1: gu = x@w1 + b1 ; act = silu(gu_even)*gu_odd   (act stored col-major)
//   GEMM2: out = act@w2 + b2
// Operands pre-rounded to tf32 (RNA): rel_err ~5e-4 (threshold 1e-3).
// ============================================================================

#define E_EXPERTS 8
#define HDIM      2048
#define IDIM      2048
#define F2I       4096
#define ROWS      4096

__device__ float g_xc [(size_t)E_EXPERTS * HDIM * ROWS];   // x col-major, rounded
__device__ float g_act[(size_t)E_EXPERTS * IDIM * ROWS];   // act col-major, rounded
__device__ float g_w1r[(size_t)E_EXPERTS * HDIM * F2I];    // w1 rounded (native [h][f])
__device__ float g_w2r[(size_t)E_EXPERTS * IDIM * HDIM];   // w2 rounded (native [i][h])

__device__ __forceinline__ float rnd_tf32(float x) {
    float y; asm("cvt.rna.tf32.f32 %0, %1;" : "=f"(y) : "f"(x)); return y;
}

__device__ __forceinline__ uint32_t smem_to_u32(const void* p) {
    uint32_t a;
    asm("{ .reg .u64 t; cvta.to.shared.u64 t, %1; cvt.u32.u64 %0, t; }" : "=r"(a) : "l"(p));
    return a;
}

__device__ __forceinline__ void cp_async16(uint32_t saddr, const void* gaddr) {
    asm volatile("cp.async.cg.shared.global [%0], [%1], 16;" :: "r"(saddr), "l"(gaddr));
}
#define CP_COMMIT() asm volatile("cp.async.commit_group;" ::: "memory")
#define CP_WAIT(N)  asm volatile("cp.async.wait_group %0;" :: "n"(N) : "memory")

#define MMA_TF32(d, a, b) \
    asm volatile("mma.sync.aligned.m16n8k8.row.col.f32.tf32.tf32.f32 " \
        "{%0,%1,%2,%3}, {%4,%5,%6,%7}, {%8,%9}, {%0,%1,%2,%3};" \
        : "+f"((d)[0]), "+f"((d)[1]), "+f"((d)[2]), "+f"((d)[3]) \
        : "r"((a)[0]), "r"((a)[1]), "r"((a)[2]), "r"((a)[3]), \
          "r"((b)[0]), "r"((b)[1]))

// ---------------- GEMM tiling ----------------
#define BM      128
#define BN      256
#define BK      32
#define STAGES  4
#define PAD     8
#define LDSA_W  (BM + PAD)                 // 136
#define LDSB_W  (BN + PAD)                 // 264
#define A_FLTS  (BK * LDSA_W)              // 4352
#define B_FLTS  (BK * LDSB_W)              // 8448
#define STG_FLTS (A_FLTS + B_FLTS)         // 12800
#define DYN_SMEM (STAGES * STG_FLTS * 4)   // 204800 B

// MODE 0: A=g_xc,  B=g_w1r (NB=4096), epilogue: bias+silu*up -> g_act (col-major)
// MODE 1: A=g_act, B=g_w2r (NB=2048), epilogue: bias -> out (row-major [e][m][h])
template <int MODE>
__global__ void __launch_bounds__(512, 1)
moe_gemm(const float* __restrict__ Amat,
         const float* __restrict__ Bmat,
         const float* __restrict__ bias,
         float* __restrict__ outp)
{
    extern __shared__ float smem[];
    const int NB = (MODE == 0) ? F2I : HDIM;
    const int tid   = threadIdx.x;
    const int mtile = blockIdx.x;              // 0..31
    const int ntile = blockIdx.y;              // 0..(NB/256-1)
    const int e     = blockIdx.z;

    const int wid  = tid >> 5;                 // 0..15
    const int lane = tid & 31;
    const int g    = lane >> 2;                // 0..7
    const int q    = lane & 3;                 // 0..3
    const int warpM = (wid & 3) * 32;          // 4 warps along M
    const int warpN = (wid >> 2) * 64;         // 4 warps along N

    const float* Abase = Amat + (size_t)e * HDIM * ROWS + mtile * BM;   // [k][m], stride ROWS
    const float* Bbase = Bmat + (size_t)e * HDIM * NB   + ntile * BN;   // [k][n], stride NB

    const uint32_t smem_u = smem_to_u32(smem);

    float acc[2][8][4];
    #pragma unroll
    for (int mt = 0; mt < 2; mt++)
        #pragma unroll
        for (int nt = 0; nt < 8; nt++)
            #pragma unroll
            for (int r = 0; r < 4; r++) acc[mt][nt][r] = 0.0f;

    // ---- stage loader: A 1024 float4, B 2048 float4, 512 threads ----
    auto load_stage = [&](int s, int c) {
        const uint32_t sbase = smem_u + (uint32_t)s * STG_FLTS * 4;
        const float* Ag = Abase + (size_t)c * BK * ROWS;
        const float* Bg = Bbase + (size_t)c * BK * NB;
        #pragma unroll
        for (int i = 0; i < 2; i++) {
            int idx = tid + i * 512;           // 0..1023
            int row = idx >> 5, col = (idx & 31) << 2;   // 32 f4 per A k-row
            cp_async16(sbase + (uint32_t)(row * LDSA_W + col) * 4,
                       Ag + (size_t)row * ROWS + col);
        }
        #pragma unroll
        for (int i = 0; i < 4; i++) {
            int idx = tid + i * 512;           // 0..2047
            int row = idx >> 6, col = (idx & 63) << 2;   // 64 f4 per B k-row
            cp_async16(sbase + (uint32_t)(A_FLTS + row * LDSB_W + col) * 4,
                       Bg + (size_t)row * NB + col);
        }
        CP_COMMIT();
    };

    const int NCHUNK = HDIM / BK;   // 64
    #pragma unroll
    for (int c = 0; c < STAGES - 1; c++) load_stage(c, c);

    for (int c = 0; c < NCHUNK; c++) {
        CP_WAIT(STAGES - 2);
        __syncthreads();
        // Prefetch target stage (c+3)&3 == (c-1)&3: its previous compute was
        // chunk c-1, and the barrier above fenced that — no trailing barrier needed.
        if (c + STAGES - 1 < NCHUNK) load_stage((c + STAGES - 1) & 3, c + STAGES - 1);

        const float* sA = smem + (c & 3) * STG_FLTS;
        const float* sB = sA + A_FLTS;
        const float* pA = sA + q * LDSA_W + warpM + g;
        const float* pB = sB + q * LDSB_W + warpN + g;

        #pragma unroll
        for (int ks = 0; ks < 4; ks++) {
            const float* a_ = pA + ks * 8 * LDSA_W;
            const float* b_ = pB + ks * 8 * LDSB_W;
            uint32_t af[2][4];
            #pragma unroll
            for (int mt = 0; mt < 2; mt++) {
                af[mt][0] = __float_as_uint(a_[mt * 16]);
                af[mt][1] = __float_as_uint(a_[mt * 16 + 8]);
                af[mt][2] = __float_as_uint(a_[4 * LDSA_W + mt * 16]);
                af[mt][3] = __float_as_uint(a_[4 * LDSA_W + mt * 16 + 8]);
            }
            uint32_t bf[8][2];
            #pragma unroll
            for (int nt = 0; nt < 8; nt++) {
                bf[nt][0] = __float_as_uint(b_[nt * 8]);
                bf[nt][1] = __float_as_uint(b_[4 * LDSB_W + nt * 8]);
            }
            #pragma unroll
            for (int mt = 0; mt < 2; mt++)
                #pragma unroll
                for (int nt = 0; nt < 8; nt++)
                    MMA_TF32(acc[mt][nt], af[mt], bf[nt]);
        }
    }
    // acc layout: c0:(row g, col 2q) c1:(g, 2q+1) c2:(g+8, 2q) c3:(g+8, 2q+1)

    if (MODE == 0) {
        const int f0 = ntile * BN + warpN;
        #pragma unroll
        for (int nt = 0; nt < 8; nt++) {
            const int fpair = f0 + nt * 8 + 2 * q;          // gate column (even)
            const float2 bgu = *reinterpret_cast<const float2*>(
                bias + (size_t)e * F2I + fpair);
            const int icol = fpair >> 1;
            float* dcol = g_act + ((size_t)e * IDIM + icol) * ROWS
                                + mtile * BM + warpM;
            #pragma unroll
            for (int mt = 0; mt < 2; mt++) {
                float gg0 = acc[mt][nt][0] + bgu.x;
                float uu0 = acc[mt][nt][1] + bgu.y;
                float gg1 = acc[mt][nt][2] + bgu.x;
                float uu1 = acc[mt][nt][3] + bgu.y;
                float a0 = (gg0 * uu0) / (1.0f + __expf(-gg0));
                float a1 = (gg1 * uu1) / (1.0f + __expf(-gg1));
                dcol[mt * 16 + g]     = rnd_tf32(a0);
                dcol[mt * 16 + g + 8] = rnd_tf32(a1);
            }
        }
    } else {
        const int h0 = ntile * BN + warpN;
        #pragma unroll
        for (int nt = 0; nt < 8; nt++) {
            const int h = h0 + nt * 8 + 2 * q;
            const float2 bb = *reinterpret_cast<const float2*>(
                bias + (size_t)e * HDIM + h);
            #pragma unroll
            for (int mt = 0; mt < 2; mt++) {
                const int m = mtile * BM + warpM + mt * 16 + g;
                float* o0 = outp + ((size_t)e * ROWS + m) * HDIM + h;
                *reinterpret_cast<float2*>(o0) =
                    make_float2(acc[mt][nt][0] + bb.x, acc[mt][nt][1] + bb.y);
                *reinterpret_cast<float2*>(o0 + 8 * (size_t)HDIM) =
                    make_float2(acc[mt][nt][2] + bb.x, acc[mt][nt][3] + bb.y);
            }
        }
    }
}

// ============================ prep kernels ============================

// dispatched [b(8)][e(8)][m(512)][h(2048)] -> g_xc [e][h][r=b*512+m], rounded
__global__ void prep_transpose_x(const float* __restrict__ in) {
    __shared__ float t[32][33];
    const int e  = blockIdx.z;
    const int r0 = blockIdx.x * 32;
    const int h0 = blockIdx.y * 32;
    #pragma unroll
    for (int j = 0; j < 4; j++) {
        int r = r0 + threadIdx.y + j * 8;
        int b = r >> 9, m = r & 511;
        t[threadIdx.y + j * 8][threadIdx.x] =
            in[(((size_t)(b * E_EXPERTS + e) << 9) + m) * HDIM + h0 + threadIdx.x];
    }
    __syncthreads();
    #pragma unroll
    for (int j = 0; j < 4; j++)
        g_xc[((size_t)e * HDIM + h0 + threadIdx.y + j * 8) * ROWS + r0 + threadIdx.x] =
            rnd_tf32(t[threadIdx.x][threadIdx.y + j * 8]);
}

__global__ void prep_round(const float4* __restrict__ in, float4* __restrict__ outp) {
    size_t i = (size_t)blockIdx.x * blockDim.x + threadIdx.x;
    float4 v = in[i];
    v.x = rnd_tf32(v.x); v.y = rnd_tf32(v.y); v.z = rnd_tf32(v.z); v.w = rnd_tf32(v.w);
    outp[i] = v;
}

// ============================ host side ============================

extern "C" void kernel_launch(void* const* d_in, const int* in_sizes, int n_in,
                              void* d_out, int out_size)
{
    const float* dispatched = (const float*)d_in[0];   // (1,8,8,512,2048)
    const float* w1_bias    = (const float*)d_in[2];   // (8,4096)
    const float* w1         = (const float*)d_in[1];   // (8,2048,4096)
    const float* w2         = (const float*)d_in[3];   // (8,2048,2048)
    const float* w2_bias    = (const float*)d_in[4];   // (8,2048)
    float* out = (float*)d_out;                        // (8,1,4096,2048) fp32
    (void)in_sizes; (void)n_in; (void)out_size;

    static float *p_xc = nullptr, *p_act = nullptr, *p_w1r = nullptr, *p_w2r = nullptr;
    static bool init_done = false;
    if (!init_done) {
        cudaGetSymbolAddress((void**)&p_xc,  g_xc);
        cudaGetSymbolAddress((void**)&p_act, g_act);
        cudaGetSymbolAddress((void**)&p_w1r, g_w1r);
        cudaGetSymbolAddress((void**)&p_w2r, g_w2r);
        cudaFuncSetAttribute(moe_gemm<0>, cudaFuncAttributeMaxDynamicSharedMemorySize, DYN_SMEM);
        cudaFuncSetAttribute(moe_gemm<1>, cudaFuncAttributeMaxDynamicSharedMemorySize, DYN_SMEM);
        init_done = true;
    }

    prep_transpose_x<<<dim3(ROWS / 32, HDIM / 32, E_EXPERTS), dim3(32, 8)>>>(dispatched);
    prep_round<<<(E_EXPERTS * (size_t)HDIM * F2I / 4) / 256, 256>>>(
        reinterpret_cast<const float4*>(w1), reinterpret_cast<float4*>(p_w1r));
    prep_round<<<(E_EXPERTS * (size_t)IDIM * HDIM / 4) / 256, 256>>>(
        reinterpret_cast<const float4*>(w2), reinterpret_cast<float4*>(p_w2r));

    // GEMM1: x @ w1 -> silu -> g_act      grid (32, 16, 8)
    moe_gemm<0><<<dim3(ROWS / BM, F2I / BN, E_EXPERTS), 512, DYN_SMEM>>>(
        p_xc, p_w1r, w1_bias, nullptr);
    // GEMM2: act @ w2 -> +bias -> out     grid (32, 8, 8)
    moe_gemm<1><<<dim3(ROWS / BM, HDIM / BN, E_EXPERTS), 512, DYN_SMEM>>>(
        p_act, p_w2r, w2_bias, out);
}

// round 5
// speedup vs baseline: 1.8581x; 1.8581x over previous
#include <cuda_runtime.h>
#include <math.h>
#include <stdint.h>

// ============================================================================
// FusedExpertsWrapper — TF32 mma.sync + cp.async.bulk (1D TMA-class) pipeline.
//   GEMM1: gu = x@w1 + b1 ; act = silu(gu_even)*gu_odd
//   GEMM2: out = act@w2 + b2
// All operands pre-packed into padded smem stage images [64][136] so each
// pipeline stage is loaded by TWO cp.async.bulk instructions (thread 0 only),
// eliminating the per-thread cp.async issue stream that starved the tensor pipe.
// Operands tf32(RNA)-rounded: rel_err ~5e-4 (threshold 1e-3).
// ============================================================================

#define E_EXPERTS 8
#define HDIM      2048
#define IDIM      2048
#define F2I       4096
#define ROWS      4096

// ---------------- tiling ----------------
#define BM      128
#define BN      128
#define BK      64
#define STAGES  3
#define PAD     8
#define LDW     (BM + PAD)                   // 136 floats per k-row
#define TILE_FLTS  (BK * LDW)                // 8704 floats = one operand block
#define TILE_BYTES (TILE_FLTS * 4)           // 34816
#define STG_FLTS   (2 * TILE_FLTS)           // 17408
#define STG_BYTES  (STG_FLTS * 4)            // 69632
#define DYN_SMEM   (STAGES * STG_BYTES)      // 208896
#define NCHUNK  (HDIM / BK)                  // 32

// ---------------- packed scratch (device globals) ----------------
// layout: [e][tile][chunk][64][136]
__device__ float g_xp  [(size_t)E_EXPERTS * 32 * NCHUNK * TILE_FLTS];  // x packed (A of GEMM1)
__device__ float g_actp[(size_t)E_EXPERTS * 32 * NCHUNK * TILE_FLTS];  // act packed (A of GEMM2)
__device__ float g_w1p [(size_t)E_EXPERTS * 32 * NCHUNK * TILE_FLTS];  // w1 packed (B of GEMM1)
__device__ float g_w2p [(size_t)E_EXPERTS * 16 * NCHUNK * TILE_FLTS];  // w2 packed (B of GEMM2)

__device__ __forceinline__ float rnd_tf32(float x) {
    float y; asm("cvt.rna.tf32.f32 %0, %1;" : "=f"(y) : "f"(x)); return y;
}
__device__ __forceinline__ uint32_t smem_to_u32(const void* p) {
    uint32_t a;
    asm("{ .reg .u64 t; cvta.to.shared.u64 t, %1; cvt.u32.u64 %0, t; }" : "=r"(a) : "l"(p));
    return a;
}

#define MBARRIER_INIT(addr, cnt) \
    asm volatile("mbarrier.init.shared.b64 [%0], %1;" :: "r"((uint32_t)(addr)), "r"((uint32_t)(cnt)) : "memory")
#define MBARRIER_EXPECT_TX(addr, bytes) \
    asm volatile("mbarrier.arrive.expect_tx.shared.b64 _, [%0], %1;" :: "r"((uint32_t)(addr)), "r"((uint32_t)(bytes)) : "memory")
#define FENCE_PROXY_ASYNC() asm volatile("fence.proxy.async.shared::cta;" ::: "memory")

#define MBARRIER_WAIT_PARITY(mbar_smem_addr, phase_parity) do { \
    uint32_t _mbar = (uint32_t)(mbar_smem_addr); \
    uint32_t _parity = (uint32_t)(phase_parity); \
    uint32_t _done; \
    asm volatile( \
        "{\n\t.reg .pred p;\n\t" \
        "mbarrier.try_wait.parity.acquire.cta.shared::cta.b64 p, [%1], %2;\n\t" \
        "selp.b32 %0, 1, 0, p;\n\t}" \
        : "=r"(_done) : "r"(_mbar), "r"(_parity) : "memory"); \
    if (!_done) { \
        asm volatile( \
            "{\n\t.reg .pred P1;\n\t" \
            "WAIT_LOOP_%=:\n\t" \
            "mbarrier.try_wait.parity.acquire.cta.shared::cta.b64 P1, [%0], %1, 0x989680;\n\t" \
            "@P1 bra.uni WAIT_DONE_%=;\n\t" \
            "bra.uni WAIT_LOOP_%=;\n\t" \
            "WAIT_DONE_%=:\n\t}" \
            :: "r"(_mbar), "r"(_parity) : "memory"); \
    } \
} while (0)

__device__ __forceinline__ void bulk_g2s(uint32_t sdst, const void* gsrc,
                                         uint32_t bytes, uint32_t mbar) {
    asm volatile(
        "cp.async.bulk.shared::cluster.global.mbarrier::complete_tx::bytes "
        "[%0], [%1], %2, [%3];"
        :: "r"(sdst), "l"(gsrc), "r"(bytes), "r"(mbar) : "memory");
}

#define MMA_TF32(d, a, b) \
    asm volatile("mma.sync.aligned.m16n8k8.row.col.f32.tf32.tf32.f32 " \
        "{%0,%1,%2,%3}, {%4,%5,%6,%7}, {%8,%9}, {%0,%1,%2,%3};" \
        : "+f"((d)[0]), "+f"((d)[1]), "+f"((d)[2]), "+f"((d)[3]) \
        : "r"((a)[0]), "r"((a)[1]), "r"((a)[2]), "r"((a)[3]), \
          "r"((b)[0]), "r"((b)[1]))

// ============================ main GEMM kernel ============================
// 256 threads = 8 warps as 2(M)x4(N); warp tile 64x32; per-warp 4x4 m16n8k8.
// MODE 0: A=g_xp, B=g_w1p (32 ntiles), epilogue bias+silu -> g_actp (packed)
// MODE 1: A=g_actp, B=g_w2p (16 ntiles), epilogue bias -> out [e][m][h]
template <int MODE>
__global__ void __launch_bounds__(256, 1)
moe_gemm(const float* __restrict__ Ap,
         const float* __restrict__ Bp,
         const float* __restrict__ bias,
         float* __restrict__ outp)
{
    extern __shared__ __align__(1024) float smem[];
    __shared__ __align__(8) unsigned long long mb[STAGES];

    const int NT    = (MODE == 0) ? 32 : 16;
    const int tid   = threadIdx.x;
    const int mtile = blockIdx.x;              // 0..31
    const int ntile = blockIdx.y;              // 0..NT-1
    const int e     = blockIdx.z;

    const int wid  = tid >> 5;
    const int lane = tid & 31;
    const int g    = lane >> 2;                // 0..7
    const int q    = lane & 3;                 // 0..3
    const int warpM = (wid & 1) * 64;          // 2 warps along M
    const int warpN = (wid >> 1) * 32;         // 4 warps along N

    const float* Abase = Ap + (((size_t)e * 32 + mtile) * NCHUNK) * TILE_FLTS;
    const float* Bbase = Bp + (((size_t)e * NT + ntile) * NCHUNK) * TILE_FLTS;

    const uint32_t smem_u = smem_to_u32(smem);
    const uint32_t mb_u   = smem_to_u32(mb);

    if (tid == 0) {
        #pragma unroll
        for (int s = 0; s < STAGES; s++) MBARRIER_INIT(mb_u + s * 8, 1);
        FENCE_PROXY_ASYNC();
    }
    __syncthreads();

    if (tid == 0) {
        #pragma unroll
        for (int p = 0; p < 2; p++) {
            MBARRIER_EXPECT_TX(mb_u + p * 8, STG_BYTES);
            bulk_g2s(smem_u + p * STG_BYTES,             Abase + (size_t)p * TILE_FLTS, TILE_BYTES, mb_u + p * 8);
            bulk_g2s(smem_u + p * STG_BYTES + TILE_BYTES, Bbase + (size_t)p * TILE_FLTS, TILE_BYTES, mb_u + p * 8);
        }
    }

    float acc[4][4][4];
    #pragma unroll
    for (int mt = 0; mt < 4; mt++)
        #pragma unroll
        for (int nt = 0; nt < 4; nt++)
            #pragma unroll
            for (int r = 0; r < 4; r++) acc[mt][nt][r] = 0.0f;

    int s = 0, sp = 2;            // current stage, prefetch stage
    for (int c = 0; c < NCHUNK; c++) {
        __syncthreads();          // all warps done computing chunk c-1
        if (tid == 0 && c + 2 < NCHUNK) {
            const int cn = c + 2;
            MBARRIER_EXPECT_TX(mb_u + sp * 8, STG_BYTES);
            bulk_g2s(smem_u + sp * STG_BYTES,              Abase + (size_t)cn * TILE_FLTS, TILE_BYTES, mb_u + sp * 8);
            bulk_g2s(smem_u + sp * STG_BYTES + TILE_BYTES, Bbase + (size_t)cn * TILE_FLTS, TILE_BYTES, mb_u + sp * 8);
        }
        MBARRIER_WAIT_PARITY(mb_u + s * 8, (c / 3) & 1);

        const float* sA = smem + s * STG_FLTS;
        const float* sB = sA + TILE_FLTS;
        const float* pA = sA + q * LDW + warpM + g;
        const float* pB = sB + q * LDW + warpN + g;

        #pragma unroll
        for (int ks = 0; ks < 8; ks++) {
            const float* a_ = pA + ks * 8 * LDW;
            const float* b_ = pB + ks * 8 * LDW;
            uint32_t af[4][4];
            #pragma unroll
            for (int mt = 0; mt < 4; mt++) {
                af[mt][0] = __float_as_uint(a_[mt * 16]);
                af[mt][1] = __float_as_uint(a_[mt * 16 + 8]);
                af[mt][2] = __float_as_uint(a_[4 * LDW + mt * 16]);
                af[mt][3] = __float_as_uint(a_[4 * LDW + mt * 16 + 8]);
            }
            uint32_t bf[4][2];
            #pragma unroll
            for (int nt = 0; nt < 4; nt++) {
                bf[nt][0] = __float_as_uint(b_[nt * 8]);
                bf[nt][1] = __float_as_uint(b_[4 * LDW + nt * 8]);
            }
            #pragma unroll
            for (int mt = 0; mt < 4; mt++)
                #pragma unroll
                for (int nt = 0; nt < 4; nt++)
                    MMA_TF32(acc[mt][nt], af[mt], bf[nt]);
        }
        s  = (s  == STAGES - 1) ? 0 : s + 1;
        sp = (sp == STAGES - 1) ? 0 : sp + 1;
    }

    // acc: c0:(row g, col 2q) c1:(g,2q+1) c2:(g+8,2q) c3:(g+8,2q+1)
    if (MODE == 0) {
        #pragma unroll
        for (int nt = 0; nt < 4; nt++) {
            const int fpair = ntile * BN + warpN + nt * 8 + 2 * q;   // even = gate
            const float2 bgu = *reinterpret_cast<const float2*>(
                bias + (size_t)e * F2I + fpair);
            const int icol = fpair >> 1;                             // 0..2047
            // packed act: [e][mtile][chunk=icol/64][kk=icol%64][136]
            float* dcol = g_actp
                + ((((size_t)e * 32 + mtile) * NCHUNK + (icol >> 6)) * 64 + (icol & 63)) * LDW
                + warpM;
            #pragma unroll
            for (int mt = 0; mt < 4; mt++) {
                float gg0 = acc[mt][nt][0] + bgu.x;
                float uu0 = acc[mt][nt][1] + bgu.y;
                float gg1 = acc[mt][nt][2] + bgu.x;
                float uu1 = acc[mt][nt][3] + bgu.y;
                float a0 = (gg0 * uu0) / (1.0f + __expf(-gg0));
                float a1 = (gg1 * uu1) / (1.0f + __expf(-gg1));
                dcol[mt * 16 + g]     = rnd_tf32(a0);
                dcol[mt * 16 + g + 8] = rnd_tf32(a1);
            }
        }
    } else {
        #pragma unroll
        for (int nt = 0; nt < 4; nt++) {
            const int h = ntile * BN + warpN + nt * 8 + 2 * q;
            const float2 bb = *reinterpret_cast<const float2*>(
                bias + (size_t)e * HDIM + h);
            #pragma unroll
            for (int mt = 0; mt < 4; mt++) {
                const int m = mtile * BM + warpM + mt * 16 + g;
                float* o0 = outp + ((size_t)e * ROWS + m) * HDIM + h;
                *reinterpret_cast<float2*>(o0) =
                    make_float2(acc[mt][nt][0] + bb.x, acc[mt][nt][1] + bb.y);
                *reinterpret_cast<float2*>(o0 + 8 * (size_t)HDIM) =
                    make_float2(acc[mt][nt][2] + bb.x, acc[mt][nt][3] + bb.y);
            }
        }
    }
}

// ============================ prep kernels ============================

// dispatched [b][e][m][h] -> g_xp [e][mtile][chunk][kk][136] (transpose + round)
__global__ void pack_x(const float* __restrict__ in) {
    __shared__ float t[32][33];
    const int e  = blockIdx.z;
    const int r0 = blockIdx.x * 32;     // m dim (4096)
    const int h0 = blockIdx.y * 32;     // k dim (2048)
    #pragma unroll
    for (int j = 0; j < 4; j++) {
        int r = r0 + threadIdx.y + j * 8;
        int b = r >> 9, m = r & 511;
        t[threadIdx.y + j * 8][threadIdx.x] =
            in[(((size_t)(b * E_EXPERTS + e) << 9) + m) * HDIM + h0 + threadIdx.x];
    }
    __syncthreads();
    #pragma unroll
    for (int j = 0; j < 4; j++) {
        int kg = h0 + threadIdx.y + j * 8;
        int mg = r0 + threadIdx.x;
        g_xp[((((size_t)e * 32 + (mg >> 7)) * NCHUNK + (kg >> 6)) * 64 + (kg & 63)) * LDW
             + (mg & 127)] = rnd_tf32(t[threadIdx.x][threadIdx.y + j * 8]);
    }
}

// weights [e][2048][NB] -> packed [e][NT][chunk][kk][136] (round, float4)
__global__ void pack_w(const float4* __restrict__ in, float* __restrict__ outp,
                       int NT, int NB) {
    size_t i = (size_t)blockIdx.x * blockDim.x + threadIdx.x;  // f4 units
    int nn4 = (int)(i & 31);
    int kk  = (int)((i >> 5) & 63);
    int c   = (int)((i >> 11) & 31);
    size_t r = i >> 16;
    int nt = (int)(r % NT);
    int e  = (int)(r / NT);
    float4 v = in[((size_t)e * 2048 + c * 64 + kk) * (NB / 4) + nt * 32 + nn4];
    v.x = rnd_tf32(v.x); v.y = rnd_tf32(v.y); v.z = rnd_tf32(v.z); v.w = rnd_tf32(v.w);
    *reinterpret_cast<float4*>(
        outp + ((((size_t)e * NT + nt) * NCHUNK + c) * 64 + kk) * LDW + nn4 * 4) = v;
}

// ============================ host side ============================

extern "C" void kernel_launch(void* const* d_in, const int* in_sizes, int n_in,
                              void* d_out, int out_size)
{
    const float* dispatched = (const float*)d_in[0];   // (1,8,8,512,2048)
    const float* w1         = (const float*)d_in[1];   // (8,2048,4096)
    const float* w1_bias    = (const float*)d_in[2];   // (8,4096)
    const float* w2         = (const float*)d_in[3];   // (8,2048,2048)
    const float* w2_bias    = (const float*)d_in[4];   // (8,2048)
    float* out = (float*)d_out;                        // (8,1,4096,2048) fp32
    (void)in_sizes; (void)n_in; (void)out_size;

    static float *p_xp = nullptr, *p_actp = nullptr, *p_w1p = nullptr, *p_w2p = nullptr;
    static bool init_done = false;
    if (!init_done) {
        cudaGetSymbolAddress((void**)&p_xp,   g_xp);
        cudaGetSymbolAddress((void**)&p_actp, g_actp);
        cudaGetSymbolAddress((void**)&p_w1p,  g_w1p);
        cudaGetSymbolAddress((void**)&p_w2p,  g_w2p);
        cudaFuncSetAttribute(moe_gemm<0>, cudaFuncAttributeMaxDynamicSharedMemorySize, DYN_SMEM);
        cudaFuncSetAttribute(moe_gemm<1>, cudaFuncAttributeMaxDynamicSharedMemorySize, DYN_SMEM);
        init_done = true;
    }

    pack_x<<<dim3(ROWS / 32, HDIM / 32, E_EXPERTS), dim3(32, 8)>>>(dispatched);
    pack_w<<<(unsigned)((size_t)E_EXPERTS * 32 * 32 * 64 * 32 / 256), 256>>>(
        reinterpret_cast<const float4*>(w1), p_w1p, 32, F2I);
    pack_w<<<(unsigned)((size_t)E_EXPERTS * 16 * 32 * 64 * 32 / 256), 256>>>(
        reinterpret_cast<const float4*>(w2), p_w2p, 16, HDIM);

    // GEMM1: grid (32 mtiles, 32 ntiles, 8 experts)
    moe_gemm<0><<<dim3(32, 32, E_EXPERTS), 256, DYN_SMEM>>>(p_xp, p_w1p, w1_bias, nullptr);
    // GEMM2: grid (32, 16, 8)
    moe_gemm<1><<<dim3(32, 16, E_EXPERTS), 256, DYN_SMEM>>>(p_actp, p_w2p, w2_bias, out);
}

// round 6
// speedup vs baseline: 1.9683x; 1.0593x over previous
#include <cuda_runtime.h>
#include <math.h>
#include <stdint.h>

// ============================================================================
// FusedExpertsWrapper — TF32 mma.sync + cp.async.bulk pipeline, 2 CTAs/SM.
//   GEMM1: gu = x@w1 + b1 ; act = silu(gu_even)*gu_odd
//   GEMM2: out = act@w2 + b2
// Operands pre-packed into padded smem stage images [32][136]; each stage is
// loaded by two cp.async.bulk ops (thread 0). BK=32 x 3 stages = 104.4 KB smem
// -> 2 CTAs/SM so chunk-boundary barrier/wait latency overlaps across CTAs.
// Operands tf32(RNA)-rounded: rel_err ~5e-4 (threshold 1e-3).
// ============================================================================

#define E_EXPERTS 8
#define HDIM      2048
#define IDIM      2048
#define F2I       4096
#define ROWS      4096

// ---------------- tiling ----------------
#define BM      128
#define BN      128
#define BK      32
#define STAGES  3
#define PAD     8
#define LDW     (BM + PAD)                   // 136 floats per k-row
#define TILE_FLTS  (BK * LDW)                // 4352 floats per operand block
#define TILE_BYTES (TILE_FLTS * 4)           // 17408
#define STG_FLTS   (2 * TILE_FLTS)           // 8704
#define STG_BYTES  (STG_FLTS * 4)            // 34816
#define DYN_SMEM   (STAGES * STG_BYTES)      // 104448 -> 2 CTAs/SM
#define NCHUNK  (HDIM / BK)                  // 64

// ---------------- packed scratch: [e][tile][chunk][32][136] ----------------
__device__ float g_xp  [(size_t)E_EXPERTS * 32 * NCHUNK * TILE_FLTS];
__device__ float g_actp[(size_t)E_EXPERTS * 32 * NCHUNK * TILE_FLTS];
__device__ float g_w1p [(size_t)E_EXPERTS * 32 * NCHUNK * TILE_FLTS];
__device__ float g_w2p [(size_t)E_EXPERTS * 16 * NCHUNK * TILE_FLTS];

__device__ __forceinline__ float rnd_tf32(float x) {
    float y; asm("cvt.rna.tf32.f32 %0, %1;" : "=f"(y) : "f"(x)); return y;
}
__device__ __forceinline__ uint32_t smem_to_u32(const void* p) {
    uint32_t a;
    asm("{ .reg .u64 t; cvta.to.shared.u64 t, %1; cvt.u32.u64 %0, t; }" : "=r"(a) : "l"(p));
    return a;
}

#define MBARRIER_INIT(addr, cnt) \
    asm volatile("mbarrier.init.shared.b64 [%0], %1;" :: "r"((uint32_t)(addr)), "r"((uint32_t)(cnt)) : "memory")
#define MBARRIER_EXPECT_TX(addr, bytes) \
    asm volatile("mbarrier.arrive.expect_tx.shared.b64 _, [%0], %1;" :: "r"((uint32_t)(addr)), "r"((uint32_t)(bytes)) : "memory")
#define FENCE_PROXY_ASYNC() asm volatile("fence.proxy.async.shared::cta;" ::: "memory")

#define MBARRIER_WAIT_PARITY(mbar_smem_addr, phase_parity) do { \
    uint32_t _mbar = (uint32_t)(mbar_smem_addr); \
    uint32_t _parity = (uint32_t)(phase_parity); \
    uint32_t _done; \
    asm volatile( \
        "{\n\t.reg .pred p;\n\t" \
        "mbarrier.try_wait.parity.acquire.cta.shared::cta.b64 p, [%1], %2;\n\t" \
        "selp.b32 %0, 1, 0, p;\n\t}" \
        : "=r"(_done) : "r"(_mbar), "r"(_parity) : "memory"); \
    if (!_done) { \
        asm volatile( \
            "{\n\t.reg .pred P1;\n\t" \
            "WAIT_LOOP_%=:\n\t" \
            "mbarrier.try_wait.parity.acquire.cta.shared::cta.b64 P1, [%0], %1, 0x989680;\n\t" \
            "@P1 bra.uni WAIT_DONE_%=;\n\t" \
            "bra.uni WAIT_LOOP_%=;\n\t" \
            "WAIT_DONE_%=:\n\t}" \
            :: "r"(_mbar), "r"(_parity) : "memory"); \
    } \
} while (0)

__device__ __forceinline__ void bulk_g2s(uint32_t sdst, const void* gsrc,
                                         uint32_t bytes, uint32_t mbar) {
    asm volatile(
        "cp.async.bulk.shared::cluster.global.mbarrier::complete_tx::bytes "
        "[%0], [%1], %2, [%3];"
        :: "r"(sdst), "l"(gsrc), "r"(bytes), "r"(mbar) : "memory");
}

#define MMA_TF32(d, a, b) \
    asm volatile("mma.sync.aligned.m16n8k8.row.col.f32.tf32.tf32.f32 " \
        "{%0,%1,%2,%3}, {%4,%5,%6,%7}, {%8,%9}, {%0,%1,%2,%3};" \
        : "+f"((d)[0]), "+f"((d)[1]), "+f"((d)[2]), "+f"((d)[3]) \
        : "r"((a)[0]), "r"((a)[1]), "r"((a)[2]), "r"((a)[3]), \
          "r"((b)[0]), "r"((b)[1]))

// ============================ main GEMM kernel ============================
// 256 threads = 8 warps as 2(M)x4(N); warp tile 64x32; per-warp 4x4 m16n8k8.
template <int MODE>
__global__ void __launch_bounds__(256, 2)
moe_gemm(const float* __restrict__ Ap,
         const float* __restrict__ Bp,
         const float* __restrict__ bias,
         float* __restrict__ outp)
{
    extern __shared__ __align__(1024) float smem[];
    __shared__ __align__(8) unsigned long long mb[STAGES];

    const int NT    = (MODE == 0) ? 32 : 16;
    const int tid   = threadIdx.x;
    const int mtile = blockIdx.x;
    const int ntile = blockIdx.y;
    const int e     = blockIdx.z;

    const int wid  = tid >> 5;
    const int lane = tid & 31;
    const int g    = lane >> 2;
    const int q    = lane & 3;
    const int warpM = (wid & 1) * 64;
    const int warpN = (wid >> 1) * 32;

    const float* Abase = Ap + (((size_t)e * 32 + mtile) * NCHUNK) * TILE_FLTS;
    const float* Bbase = Bp + (((size_t)e * NT + ntile) * NCHUNK) * TILE_FLTS;

    const uint32_t smem_u = smem_to_u32(smem);
    const uint32_t mb_u   = smem_to_u32(mb);

    if (tid == 0) {
        #pragma unroll
        for (int s = 0; s < STAGES; s++) MBARRIER_INIT(mb_u + s * 8, 1);
        FENCE_PROXY_ASYNC();
    }
    __syncthreads();

    if (tid == 0) {
        #pragma unroll
        for (int p = 0; p < 2; p++) {
            MBARRIER_EXPECT_TX(mb_u + p * 8, STG_BYTES);
            bulk_g2s(smem_u + p * STG_BYTES,              Abase + (size_t)p * TILE_FLTS, TILE_BYTES, mb_u + p * 8);
            bulk_g2s(smem_u + p * STG_BYTES + TILE_BYTES, Bbase + (size_t)p * TILE_FLTS, TILE_BYTES, mb_u + p * 8);
        }
    }

    float acc[4][4][4];
    #pragma unroll
    for (int mt = 0; mt < 4; mt++)
        #pragma unroll
        for (int nt = 0; nt < 4; nt++)
            #pragma unroll
            for (int r = 0; r < 4; r++) acc[mt][nt][r] = 0.0f;

    int s = 0, sp = 2;
    for (int c = 0; c < NCHUNK; c++) {
        __syncthreads();          // all warps done with chunk c-1 (stage sp)
        if (tid == 0 && c + 2 < NCHUNK) {
            const int cn = c + 2;
            MBARRIER_EXPECT_TX(mb_u + sp * 8, STG_BYTES);
            bulk_g2s(smem_u + sp * STG_BYTES,              Abase + (size_t)cn * TILE_FLTS, TILE_BYTES, mb_u + sp * 8);
            bulk_g2s(smem_u + sp * STG_BYTES + TILE_BYTES, Bbase + (size_t)cn * TILE_FLTS, TILE_BYTES, mb_u + sp * 8);
        }
        MBARRIER_WAIT_PARITY(mb_u + s * 8, (c / 3) & 1);

        const float* sA = smem + s * STG_FLTS;
        const float* sB = sA + TILE_FLTS;
        const float* pA = sA + q * LDW + warpM + g;
        const float* pB = sB + q * LDW + warpN + g;

        #pragma unroll
        for (int ks = 0; ks < 4; ks++) {
            const float* a_ = pA + ks * 8 * LDW;
            const float* b_ = pB + ks * 8 * LDW;
            uint32_t af[4][4];
            #pragma unroll
            for (int mt = 0; mt < 4; mt++) {
                af[mt][0] = __float_as_uint(a_[mt * 16]);
                af[mt][1] = __float_as_uint(a_[mt * 16 + 8]);
                af[mt][2] = __float_as_uint(a_[4 * LDW + mt * 16]);
                af[mt][3] = __float_as_uint(a_[4 * LDW + mt * 16 + 8]);
            }
            uint32_t bf[4][2];
            #pragma unroll
            for (int nt = 0; nt < 4; nt++) {
                bf[nt][0] = __float_as_uint(b_[nt * 8]);
                bf[nt][1] = __float_as_uint(b_[4 * LDW + nt * 8]);
            }
            #pragma unroll
            for (int mt = 0; mt < 4; mt++)
                #pragma unroll
                for (int nt = 0; nt < 4; nt++)
                    MMA_TF32(acc[mt][nt], af[mt], bf[nt]);
        }
        s  = (s  == STAGES - 1) ? 0 : s + 1;
        sp = (sp == STAGES - 1) ? 0 : sp + 1;
    }

    // acc: c0:(row g, col 2q) c1:(g,2q+1) c2:(g+8,2q) c3:(g+8,2q+1)
    if (MODE == 0) {
        #pragma unroll
        for (int nt = 0; nt < 4; nt++) {
            const int fpair = ntile * BN + warpN + nt * 8 + 2 * q;   // even = gate
            const float2 bgu = *reinterpret_cast<const float2*>(
                bias + (size_t)e * F2I + fpair);
            const int icol = fpair >> 1;                             // 0..2047
            // packed act: [e][mtile][chunk=icol/32][kk=icol%32][136]
            float* dcol = g_actp
                + ((((size_t)e * 32 + mtile) * NCHUNK + (icol >> 5)) * 32 + (icol & 31)) * LDW
                + warpM;
            #pragma unroll
            for (int mt = 0; mt < 4; mt++) {
                float gg0 = acc[mt][nt][0] + bgu.x;
                float uu0 = acc[mt][nt][1] + bgu.y;
                float gg1 = acc[mt][nt][2] + bgu.x;
                float uu1 = acc[mt][nt][3] + bgu.y;
                float a0 = (gg0 * uu0) / (1.0f + __expf(-gg0));
                float a1 = (gg1 * uu1) / (1.0f + __expf(-gg1));
                dcol[mt * 16 + g]     = rnd_tf32(a0);
                dcol[mt * 16 + g + 8] = rnd_tf32(a1);
            }
        }
    } else {
        #pragma unroll
        for (int nt = 0; nt < 4; nt++) {
            const int h = ntile * BN + warpN + nt * 8 + 2 * q;
            const float2 bb = *reinterpret_cast<const float2*>(
                bias + (size_t)e * HDIM + h);
            #pragma unroll
            for (int mt = 0; mt < 4; mt++) {
                const int m = mtile * BM + warpM + mt * 16 + g;
                float* o0 = outp + ((size_t)e * ROWS + m) * HDIM + h;
                *reinterpret_cast<float2*>(o0) =
                    make_float2(acc[mt][nt][0] + bb.x, acc[mt][nt][1] + bb.y);
                *reinterpret_cast<float2*>(o0 + 8 * (size_t)HDIM) =
                    make_float2(acc[mt][nt][2] + bb.x, acc[mt][nt][3] + bb.y);
            }
        }
    }
}

// ============================ prep kernels ============================

// dispatched [b][e][m][h] -> g_xp [e][mtile][chunk][kk][136]
__global__ void pack_x(const float* __restrict__ in) {
    __shared__ float t[32][33];
    const int e  = blockIdx.z;
    const int r0 = blockIdx.x * 32;     // m dim
    const int h0 = blockIdx.y * 32;     // k dim
    #pragma unroll
    for (int j = 0; j < 4; j++) {
        int r = r0 + threadIdx.y + j * 8;
        int b = r >> 9, m = r & 511;
        t[threadIdx.y + j * 8][threadIdx.x] =
            in[(((size_t)(b * E_EXPERTS + e) << 9) + m) * HDIM + h0 + threadIdx.x];
    }
    __syncthreads();
    #pragma unroll
    for (int j = 0; j < 4; j++) {
        int kg = h0 + threadIdx.y + j * 8;
        int mg = r0 + threadIdx.x;
        g_xp[((((size_t)e * 32 + (mg >> 7)) * NCHUNK + (kg >> 5)) * 32 + (kg & 31)) * LDW
             + (mg & 127)] = rnd_tf32(t[threadIdx.x][threadIdx.y + j * 8]);
    }
}

// weights [e][2048][NB] -> packed [e][NT][chunk][kk][136]
__global__ void pack_w(const float4* __restrict__ in, float* __restrict__ outp,
                       int NT, int NB) {
    size_t i = (size_t)blockIdx.x * blockDim.x + threadIdx.x;  // f4 units
    int nn4 = (int)(i & 31);            // 32 f4 per k-row segment
    int kk  = (int)((i >> 5) & 31);     // 32 k rows per chunk
    int c   = (int)((i >> 10) & 63);    // 64 chunks
    size_t r = i >> 16;
    int nt = (int)(r % NT);
    int e  = (int)(r / NT);
    float4 v = in[((size_t)e * 2048 + c * 32 + kk) * (NB / 4) + nt * 32 + nn4];
    v.x = rnd_tf32(v.x); v.y = rnd_tf32(v.y); v.z = rnd_tf32(v.z); v.w = rnd_tf32(v.w);
    *reinterpret_cast<float4*>(
        outp + ((((size_t)e * NT + nt) * NCHUNK + c) * 32 + kk) * LDW + nn4 * 4) = v;
}

// ============================ host side ============================

extern "C" void kernel_launch(void* const* d_in, const int* in_sizes, int n_in,
                              void* d_out, int out_size)
{
    const float* dispatched = (const float*)d_in[0];   // (1,8,8,512,2048)
    const float* w1         = (const float*)d_in[1];   // (8,2048,4096)
    const float* w1_bias    = (const float*)d_in[2];   // (8,4096)
    const float* w2         = (const float*)d_in[3];   // (8,2048,2048)
    const float* w2_bias    = (const float*)d_in[4];   // (8,2048)
    float* out = (float*)d_out;                        // (8,1,4096,2048) fp32
    (void)in_sizes; (void)n_in; (void)out_size;

    static float *p_xp = nullptr, *p_actp = nullptr, *p_w1p = nullptr, *p_w2p = nullptr;
    static bool init_done = false;
    if (!init_done) {
        cudaGetSymbolAddress((void**)&p_xp,   g_xp);
        cudaGetSymbolAddress((void**)&p_actp, g_actp);
        cudaGetSymbolAddress((void**)&p_w1p,  g_w1p);
        cudaGetSymbolAddress((void**)&p_w2p,  g_w2p);
        cudaFuncSetAttribute(moe_gemm<0>, cudaFuncAttributeMaxDynamicSharedMemorySize, DYN_SMEM);
        cudaFuncSetAttribute(moe_gemm<1>, cudaFuncAttributeMaxDynamicSharedMemorySize, DYN_SMEM);
        init_done = true;
    }

    pack_x<<<dim3(ROWS / 32, HDIM / 32, E_EXPERTS), dim3(32, 8)>>>(dispatched);
    pack_w<<<(unsigned)((size_t)E_EXPERTS * 32 * 64 * 32 * 32 / 256), 256>>>(
        reinterpret_cast<const float4*>(w1), p_w1p, 32, F2I);
    pack_w<<<(unsigned)((size_t)E_EXPERTS * 16 * 64 * 32 * 32 / 256), 256>>>(
        reinterpret_cast<const float4*>(w2), p_w2p, 16, HDIM);

    // GEMM1: grid (32 mtiles, 32 ntiles, 8 experts)
    moe_gemm<0><<<dim3(32, 32, E_EXPERTS), 256, DYN_SMEM>>>(p_xp, p_w1p, w1_bias, nullptr);
    // GEMM2: grid (32, 16, 8)
    moe_gemm<1><<<dim3(32, 16, E_EXPERTS), 256, DYN_SMEM>>>(p_actp, p_w2p, w2_bias, out);
}

// round 7
// speedup vs baseline: 2.1380x; 1.0862x over previous
#include <cuda_runtime.h>
#include <math.h>
#include <stdint.h>

// ============================================================================
// FusedExpertsWrapper — TF32 mma.sync + cp.async.bulk, warp-autonomous pipeline.
//   GEMM1: gu = x@w1 + b1 ; act = silu(gu_even)*gu_odd
//   GEMM2: out = act@w2 + b2
// vs R6: the per-chunk __syncthreads is replaced by per-stage empty mbarriers
// (8 warp arrivals). Warps proceed independently; producer (thread 0) waits
// empty[s] (relaxed) before re-issuing the 2 bulk loads for a stage.
// 2 CTAs/SM (104.4 KB smem). Operands tf32(RNA)-rounded: rel_err ~5e-4.
// ============================================================================

#define E_EXPERTS 8
#define HDIM      2048
#define IDIM      2048
#define F2I       4096
#define ROWS      4096

// ---------------- tiling ----------------
#define BM      128
#define BN      128
#define BK      32
#define STAGES  3
#define PAD     8
#define LDW     (BM + PAD)                   // 136 floats per k-row
#define TILE_FLTS  (BK * LDW)                // 4352
#define TILE_BYTES (TILE_FLTS * 4)           // 17408
#define STG_FLTS   (2 * TILE_FLTS)           // 8704
#define STG_BYTES  (STG_FLTS * 4)            // 34816
#define DYN_SMEM   (STAGES * STG_BYTES)      // 104448 -> 2 CTAs/SM
#define NCHUNK  (HDIM / BK)                  // 64

// ---------------- packed scratch: [e][tile][chunk][32][136] ----------------
__device__ float g_xp  [(size_t)E_EXPERTS * 32 * NCHUNK * TILE_FLTS];
__device__ float g_actp[(size_t)E_EXPERTS * 32 * NCHUNK * TILE_FLTS];
__device__ float g_w1p [(size_t)E_EXPERTS * 32 * NCHUNK * TILE_FLTS];
__device__ float g_w2p [(size_t)E_EXPERTS * 16 * NCHUNK * TILE_FLTS];

__device__ __forceinline__ float rnd_tf32(float x) {
    float y; asm("cvt.rna.tf32.f32 %0, %1;" : "=f"(y) : "f"(x)); return y;
}
__device__ __forceinline__ uint32_t smem_to_u32(const void* p) {
    uint32_t a;
    asm("{ .reg .u64 t; cvta.to.shared.u64 t, %1; cvt.u32.u64 %0, t; }" : "=r"(a) : "l"(p));
    return a;
}

#define MBARRIER_INIT(addr, cnt) \
    asm volatile("mbarrier.init.shared.b64 [%0], %1;" :: "r"((uint32_t)(addr)), "r"((uint32_t)(cnt)) : "memory")
#define MBARRIER_EXPECT_TX(addr, bytes) \
    asm volatile("mbarrier.arrive.expect_tx.shared.b64 _, [%0], %1;" :: "r"((uint32_t)(addr)), "r"((uint32_t)(bytes)) : "memory")
#define MBARRIER_ARRIVE(addr) \
    asm volatile("mbarrier.arrive.shared.b64 _, [%0];" :: "r"((uint32_t)(addr)) : "memory")
#define FENCE_PROXY_ASYNC() asm volatile("fence.proxy.async.shared::cta;" ::: "memory")

#define MBARRIER_WAIT_PARITY(mbar_smem_addr, phase_parity) do { \
    uint32_t _mbar = (uint32_t)(mbar_smem_addr); \
    uint32_t _parity = (uint32_t)(phase_parity); \
    uint32_t _done; \
    asm volatile( \
        "{\n\t.reg .pred p;\n\t" \
        "mbarrier.try_wait.parity.acquire.cta.shared::cta.b64 p, [%1], %2;\n\t" \
        "selp.b32 %0, 1, 0, p;\n\t}" \
        : "=r"(_done) : "r"(_mbar), "r"(_parity) : "memory"); \
    if (!_done) { \
        asm volatile( \
            "{\n\t.reg .pred P1;\n\t" \
            "WAIT_LOOP_%=:\n\t" \
            "mbarrier.try_wait.parity.acquire.cta.shared::cta.b64 P1, [%0], %1, 0x989680;\n\t" \
            "@P1 bra.uni WAIT_DONE_%=;\n\t" \
            "bra.uni WAIT_LOOP_%=;\n\t" \
            "WAIT_DONE_%=:\n\t}" \
            :: "r"(_mbar), "r"(_parity) : "memory"); \
    } \
} while (0)

#define MBARRIER_WAIT_PARITY_RELAXED(mbar_smem_addr, phase_parity) do { \
    uint32_t _mbar = (uint32_t)(mbar_smem_addr); \
    uint32_t _parity = (uint32_t)(phase_parity); \
    uint32_t _done; \
    asm volatile( \
        "{\n\t.reg .pred p;\n\t" \
        "mbarrier.try_wait.parity.relaxed.cta.shared::cta.b64 p, [%1], %2, 0x989680;\n\t" \
        "selp.b32 %0, 1, 0, p;\n\t}" \
        : "=r"(_done) : "r"(_mbar), "r"(_parity) : "memory"); \
    if (!_done) { \
        asm volatile( \
            "{\n\t.reg .pred P1;\n\t" \
            "WAIT_LOOP_%=:\n\t" \
            "mbarrier.try_wait.parity.relaxed.cta.shared::cta.b64 P1, [%0], %1, 0x989680;\n\t" \
            "@P1 bra.uni WAIT_DONE_%=;\n\t" \
            "bra.uni WAIT_LOOP_%=;\n\t" \
            "WAIT_DONE_%=:\n\t}" \
            :: "r"(_mbar), "r"(_parity) : "memory"); \
    } \
} while (0)

__device__ __forceinline__ void bulk_g2s(uint32_t sdst, const void* gsrc,
                                         uint32_t bytes, uint32_t mbar) {
    asm volatile(
        "cp.async.bulk.shared::cluster.global.mbarrier::complete_tx::bytes "
        "[%0], [%1], %2, [%3];"
        :: "r"(sdst), "l"(gsrc), "r"(bytes), "r"(mbar) : "memory");
}

#define MMA_TF32(d, a, b) \
    asm volatile("mma.sync.aligned.m16n8k8.row.col.f32.tf32.tf32.f32 " \
        "{%0,%1,%2,%3}, {%4,%5,%6,%7}, {%8,%9}, {%0,%1,%2,%3};" \
        : "+f"((d)[0]), "+f"((d)[1]), "+f"((d)[2]), "+f"((d)[3]) \
        : "r"((a)[0]), "r"((a)[1]), "r"((a)[2]), "r"((a)[3]), \
          "r"((b)[0]), "r"((b)[1]))

// ============================ main GEMM kernel ============================
// 256 threads = 8 warps as 2(M)x4(N); warp tile 64x32; per-warp 4x4 m16n8k8.
template <int MODE>
__global__ void __launch_bounds__(256, 2)
moe_gemm(const float* __restrict__ Ap,
         const float* __restrict__ Bp,
         const float* __restrict__ bias,
         float* __restrict__ outp)
{
    extern __shared__ __align__(1024) float smem[];
    __shared__ __align__(8) unsigned long long mb[2 * STAGES];   // full[0..2], empty[3..5]

    const int NT    = (MODE == 0) ? 32 : 16;
    const int tid   = threadIdx.x;
    const int mtile = blockIdx.x;
    const int ntile = blockIdx.y;
    const int e     = blockIdx.z;

    const int wid  = tid >> 5;
    const int lane = tid & 31;
    const int g    = lane >> 2;
    const int q    = lane & 3;
    const int warpM = (wid & 1) * 64;
    const int warpN = (wid >> 1) * 32;

    const float* Abase = Ap + (((size_t)e * 32 + mtile) * NCHUNK) * TILE_FLTS;
    const float* Bbase = Bp + (((size_t)e * NT + ntile) * NCHUNK) * TILE_FLTS;

    const uint32_t smem_u = smem_to_u32(smem);
    const uint32_t mb_u   = smem_to_u32(mb);
    #define FULL_MB(s)  (mb_u + (s) * 8u)
    #define EMPTY_MB(s) (mb_u + (STAGES + (s)) * 8u)

    if (tid == 0) {
        #pragma unroll
        for (int s = 0; s < STAGES; s++) {
            MBARRIER_INIT(FULL_MB(s), 1);
            MBARRIER_INIT(EMPTY_MB(s), 8);    // one arrive per warp
        }
        FENCE_PROXY_ASYNC();
    }
    __syncthreads();   // mbarrier init visible to all warps (only CTA-wide barrier)

    if (tid == 0) {
        #pragma unroll
        for (int p = 0; p < 2; p++) {
            MBARRIER_EXPECT_TX(FULL_MB(p), STG_BYTES);
            bulk_g2s(smem_u + p * STG_BYTES,              Abase + (size_t)p * TILE_FLTS, TILE_BYTES, FULL_MB(p));
            bulk_g2s(smem_u + p * STG_BYTES + TILE_BYTES, Bbase + (size_t)p * TILE_FLTS, TILE_BYTES, FULL_MB(p));
        }
    }

    float acc[4][4][4];
    #pragma unroll
    for (int mt = 0; mt < 4; mt++)
        #pragma unroll
        for (int nt = 0; nt < 4; nt++)
            #pragma unroll
            for (int r = 0; r < 4; r++) acc[mt][nt][r] = 0.0f;

    int s = 0;
    for (int c = 0; c < NCHUNK; c++) {
        // producer: refill stage sp=(c+2)%3 once its previous consumer (chunk c-1) drained
        if (tid == 0) {
            const int cn = c + 2;
            if (cn < NCHUNK) {
                const int sp = (cn >= 3) ? (cn - 3) % 3 + 3 - 3 : cn;  // cn%3
                const int spp = cn % 3;
                if (c >= 1) {
                    const int k = cn / 3;                    // reload index
                    MBARRIER_WAIT_PARITY_RELAXED(EMPTY_MB(spp), (k + 1) & 1);
                }
                MBARRIER_EXPECT_TX(FULL_MB(spp), STG_BYTES);
                bulk_g2s(smem_u + spp * STG_BYTES,              Abase + (size_t)cn * TILE_FLTS, TILE_BYTES, FULL_MB(spp));
                bulk_g2s(smem_u + spp * STG_BYTES + TILE_BYTES, Bbase + (size_t)cn * TILE_FLTS, TILE_BYTES, FULL_MB(spp));
                (void)sp;
            }
        }

        MBARRIER_WAIT_PARITY(FULL_MB(s), (c / 3) & 1);

        const float* sA = smem + s * STG_FLTS;
        const float* sB = sA + TILE_FLTS;
        const float* pA = sA + q * LDW + warpM + g;
        const float* pB = sB + q * LDW + warpN + g;

        #pragma unroll
        for (int ks = 0; ks < 4; ks++) {
            const float* a_ = pA + ks * 8 * LDW;
            const float* b_ = pB + ks * 8 * LDW;
            uint32_t af[4][4];
            #pragma unroll
            for (int mt = 0; mt < 4; mt++) {
                af[mt][0] = __float_as_uint(a_[mt * 16]);
                af[mt][1] = __float_as_uint(a_[mt * 16 + 8]);
                af[mt][2] = __float_as_uint(a_[4 * LDW + mt * 16]);
                af[mt][3] = __float_as_uint(a_[4 * LDW + mt * 16 + 8]);
            }
            uint32_t bf[4][2];
            #pragma unroll
            for (int nt = 0; nt < 4; nt++) {
                bf[nt][0] = __float_as_uint(b_[nt * 8]);
                bf[nt][1] = __float_as_uint(b_[4 * LDW + nt * 8]);
            }
            #pragma unroll
            for (int mt = 0; mt < 4; mt++)
                #pragma unroll
                for (int nt = 0; nt < 4; nt++)
                    MMA_TF32(acc[mt][nt], af[mt], bf[nt]);
        }

        // this warp is done reading stage s
        __syncwarp();
        if (lane == 0) MBARRIER_ARRIVE(EMPTY_MB(s));

        s = (s == STAGES - 1) ? 0 : s + 1;
    }

    // acc: c0:(row g, col 2q) c1:(g,2q+1) c2:(g+8,2q) c3:(g+8,2q+1)
    if (MODE == 0) {
        #pragma unroll
        for (int nt = 0; nt < 4; nt++) {
            const int fpair = ntile * BN + warpN + nt * 8 + 2 * q;   // even = gate
            const float2 bgu = *reinterpret_cast<const float2*>(
                bias + (size_t)e * F2I + fpair);
            const int icol = fpair >> 1;                             // 0..2047
            float* dcol = g_actp
                + ((((size_t)e * 32 + mtile) * NCHUNK + (icol >> 5)) * 32 + (icol & 31)) * LDW
                + warpM;
            #pragma unroll
            for (int mt = 0; mt < 4; mt++) {
                float gg0 = acc[mt][nt][0] + bgu.x;
                float uu0 = acc[mt][nt][1] + bgu.y;
                float gg1 = acc[mt][nt][2] + bgu.x;
                float uu1 = acc[mt][nt][3] + bgu.y;
                float a0 = (gg0 * uu0) / (1.0f + __expf(-gg0));
                float a1 = (gg1 * uu1) / (1.0f + __expf(-gg1));
                dcol[mt * 16 + g]     = rnd_tf32(a0);
                dcol[mt * 16 + g + 8] = rnd_tf32(a1);
            }
        }
    } else {
        #pragma unroll
        for (int nt = 0; nt < 4; nt++) {
            const int h = ntile * BN + warpN + nt * 8 + 2 * q;
            const float2 bb = *reinterpret_cast<const float2*>(
                bias + (size_t)e * HDIM + h);
            #pragma unroll
            for (int mt = 0; mt < 4; mt++) {
                const int m = mtile * BM + warpM + mt * 16 + g;
                float* o0 = outp + ((size_t)e * ROWS + m) * HDIM + h;
                *reinterpret_cast<float2*>(o0) =
                    make_float2(acc[mt][nt][0] + bb.x, acc[mt][nt][1] + bb.y);
                *reinterpret_cast<float2*>(o0 + 8 * (size_t)HDIM) =
                    make_float2(acc[mt][nt][2] + bb.x, acc[mt][nt][3] + bb.y);
            }
        }
    }
}

// ============================ prep kernels ============================

// dispatched [b][e][m][h] -> g_xp [e][mtile][chunk][kk][136]
__global__ void pack_x(const float* __restrict__ in) {
    __shared__ float t[32][33];
    const int e  = blockIdx.z;
    const int r0 = blockIdx.x * 32;     // m dim
    const int h0 = blockIdx.y * 32;     // k dim
    #pragma unroll
    for (int j = 0; j < 4; j++) {
        int r = r0 + threadIdx.y + j * 8;
        int b = r >> 9, m = r & 511;
        t[threadIdx.y + j * 8][threadIdx.x] =
            in[(((size_t)(b * E_EXPERTS + e) << 9) + m) * HDIM + h0 + threadIdx.x];
    }
    __syncthreads();
    #pragma unroll
    for (int j = 0; j < 4; j++) {
        int kg = h0 + threadIdx.y + j * 8;
        int mg = r0 + threadIdx.x;
        g_xp[((((size_t)e * 32 + (mg >> 7)) * NCHUNK + (kg >> 5)) * 32 + (kg & 31)) * LDW
             + (mg & 127)] = rnd_tf32(t[threadIdx.x][threadIdx.y + j * 8]);
    }
}

// weights [e][2048][NB] -> packed [e][NT][chunk][kk][136]
__global__ void pack_w(const float4* __restrict__ in, float* __restrict__ outp,
                       int NT, int NB) {
    size_t i = (size_t)blockIdx.x * blockDim.x + threadIdx.x;  // f4 units
    int nn4 = (int)(i & 31);
    int kk  = (int)((i >> 5) & 31);
    int c   = (int)((i >> 10) & 63);
    size_t r = i >> 16;
    int nt = (int)(r % NT);
    int e  = (int)(r / NT);
    float4 v = in[((size_t)e * 2048 + c * 32 + kk) * (NB / 4) + nt * 32 + nn4];
    v.x = rnd_tf32(v.x); v.y = rnd_tf32(v.y); v.z = rnd_tf32(v.z); v.w = rnd_tf32(v.w);
    *reinterpret_cast<float4*>(
        outp + ((((size_t)e * NT + nt) * NCHUNK + c) * 32 + kk) * LDW + nn4 * 4) = v;
}

// ============================ host side ============================

extern "C" void kernel_launch(void* const* d_in, const int* in_sizes, int n_in,
                              void* d_out, int out_size)
{
    const float* dispatched = (const float*)d_in[0];   // (1,8,8,512,2048)
    const float* w1         = (const float*)d_in[1];   // (8,2048,4096)
    const float* w1_bias    = (const float*)d_in[2];   // (8,4096)
    const float* w2         = (const float*)d_in[3];   // (8,2048,2048)
    const float* w2_bias    = (const float*)d_in[4];   // (8,2048)
    float* out = (float*)d_out;                        // (8,1,4096,2048) fp32
    (void)in_sizes; (void)n_in; (void)out_size;

    static float *p_xp = nullptr, *p_actp = nullptr, *p_w1p = nullptr, *p_w2p = nullptr;
    static bool init_done = false;
    if (!init_done) {
        cudaGetSymbolAddress((void**)&p_xp,   g_xp);
        cudaGetSymbolAddress((void**)&p_actp, g_actp);
        cudaGetSymbolAddress((void**)&p_w1p,  g_w1p);
        cudaGetSymbolAddress((void**)&p_w2p,  g_w2p);
        cudaFuncSetAttribute(moe_gemm<0>, cudaFuncAttributeMaxDynamicSharedMemorySize, DYN_SMEM);
        cudaFuncSetAttribute(moe_gemm<1>, cudaFuncAttributeMaxDynamicSharedMemorySize, DYN_SMEM);
        init_done = true;
    }

    pack_x<<<dim3(ROWS / 32, HDIM / 32, E_EXPERTS), dim3(32, 8)>>>(dispatched);
    pack_w<<<(unsigned)((size_t)E_EXPERTS * 32 * 64 * 32 * 32 / 256), 256>>>(
        reinterpret_cast<const float4*>(w1), p_w1p, 32, F2I);
    pack_w<<<(unsigned)((size_t)E_EXPERTS * 16 * 64 * 32 * 32 / 256), 256>>>(
        reinterpret_cast<const float4*>(w2), p_w2p, 16, HDIM);

    // GEMM1: grid (32 mtiles, 32 ntiles, 8 experts)
    moe_gemm<0><<<dim3(32, 32, E_EXPERTS), 256, DYN_SMEM>>>(p_xp, p_w1p, w1_bias, nullptr);
    // GEMM2: grid (32, 16, 8)
    moe_gemm<1><<<dim3(32, 16, E_EXPERTS), 256, DYN_SMEM>>>(p_actp, p_w2p, w2_bias, out);
}